// round 11
// baseline (speedup 1.0000x reference)
#include <cuda_runtime.h>
#include <cuda_bf16.h>
#include <math.h>

// Problem constants (from reference): N=500000, E=16000000, IN_DIM=17
#define NMAX 500000
#define IN_DIM 17

// Fixed-point packing: per-edge encoded value = round(msg * 2^24) + 2^40.
// Accumulator = cnt*2^40 + sum_fixed, |sum_fixed| < 2^39 always.
#define FIX_SCALE 16777216.0f           // 2^24
#define FIX_INV   (1.0f / 16777216.0f)
#define CNT_SHIFT 40

// Scratch (allocation-free rule: __device__ globals)
__device__ __align__(16) unsigned long long g_accum[NMAX];  // {count, fixed sum}
__device__ __align__(16) float g_projl[NMAX];               // x @ w_l^T
__device__ __align__(16) float g_projr[NMAX];               // x @ w_r^T
__device__ int g_use64;                                     // edge_index is int64?

// ---------------------------------------------------------------------------
// Kernel 1: per-node projections + zero accumulator + (block 0) dtype probe.
// Measured-best variant: block-cooperative float4 staging of the 256-node
// x tile into smem (stride 17 is coprime with 32 -> conflict-free LDS).
// __ldcs keeps the read-once 34 MB x stream from evicting projl/accum
// (written here, consumed by k_edge) out of L2.
// All k_proj shapes measure ~12-13us (~2.7 TB/s) — short-kernel DRAM
// ceiling, so this kernel is considered done.
// ---------------------------------------------------------------------------
#define PROJ_TPB 256
#define TILE_FLOATS (PROJ_TPB * IN_DIM)      // 4352
#define TILE_F4     (TILE_FLOATS / 4)        // 1088

__global__ void k_proj(const float4* __restrict__ x4, long long totalF4,
                       const float* __restrict__ wl,
                       const float* __restrict__ wr,
                       const long long* __restrict__ ei,
                       int n) {
    __shared__ float s_x[TILE_FLOATS];

    if (blockIdx.x == 0 && threadIdx.x < 32) {
        // JAX without x64 silently downgrades the requested int64 edge_index
        // to int32; random int32 pairs read as int64 exceed [0,N) w.p. ~1.
        int bad = 0;
        for (int i = threadIdx.x; i < 2048; i += 32) {
            long long v = ei[i];
            if (v < 0 || v >= (long long)n) bad = 1;
        }
        bad = __any_sync(0xFFFFFFFFu, bad);
        if (threadIdx.x == 0) g_use64 = bad ? 0 : 1;
    }

    long long base4 = (long long)blockIdx.x * TILE_F4;
#pragma unroll
    for (int j = 0; j < TILE_F4 / PROJ_TPB + 1; j++) {
        int li = j * PROJ_TPB + threadIdx.x;
        if (li < TILE_F4 && base4 + li < totalF4) {
            float4 v = __ldcs(&x4[base4 + li]);
            ((float4*)s_x)[li] = v;
        }
    }
    __syncthreads();

    int i = blockIdx.x * PROJ_TPB + threadIdx.x;
    if (i >= n) return;
    const float* xi = s_x + threadIdx.x * IN_DIM;
    float pl = 0.f, pr = 0.f;
#pragma unroll
    for (int k = 0; k < IN_DIM; k++) {
        float v = xi[k];
        pl = fmaf(v, __ldg(&wl[k]), pl);
        pr = fmaf(v, __ldg(&wr[k]), pr);
    }
    g_projl[i] = pl;
    g_projr[i] = pr;
    g_accum[i] = 0ULL;
}

// ---------------------------------------------------------------------------
// Kernel 2: edge scatter. 8 edges/thread (EPT=16 regressed; 8 is the sweet
// spot). Phase order maximizes MLP: vector-load all indices, issue ALL 8
// gathers of proj_l, then fire 8 fire-and-forget u64 REDs (packed fixed-
// point sum + count). Bound: LTS sector throughput — gather 16M + RED 16M
// 32B sectors ~= 1 GB of L2 traffic, ~90% of the chip LTS cap. FROZEN.
// ---------------------------------------------------------------------------
#define EPT 8

__device__ __forceinline__ void red_add_u64(unsigned long long* addr,
                                            unsigned long long v) {
    asm volatile("red.global.add.u64 [%0], %1;" :: "l"(addr), "l"(v) : "memory");
}

__device__ __forceinline__ unsigned long long pack_msg(float msg) {
    return (unsigned long long)(llrintf(msg * FIX_SCALE) + (1LL << CNT_SHIFT));
}

__global__ void k_edge(const void* __restrict__ ei_raw, long long E, int n) {
    long long base = (long long)EPT * ((long long)blockIdx.x * blockDim.x + threadIdx.x);
    if (base >= E) return;

    if (!g_use64) {
        // ---- int32 fast path (expected) ----
        const int* p = (const int*)ei_raw;
        if (base + EPT <= E) {
            int s[EPT], d[EPT];
#pragma unroll
            for (int j = 0; j < EPT; j += 4) {
                int4 sv = __ldcs((const int4*)(p + base + j));
                s[j] = sv.x; s[j + 1] = sv.y; s[j + 2] = sv.z; s[j + 3] = sv.w;
            }
#pragma unroll
            for (int j = 0; j < EPT; j += 4) {
                int4 dv = __ldcs((const int4*)(p + E + base + j));
                d[j] = dv.x; d[j + 1] = dv.y; d[j + 2] = dv.z; d[j + 3] = dv.w;
            }
            float m[EPT];
            bool ok[EPT];
#pragma unroll
            for (int j = 0; j < EPT; j++) {
                ok[j] = (unsigned)s[j] < (unsigned)n && (unsigned)d[j] < (unsigned)n;
                m[j] = ok[j] ? g_projl[s[j]] : 0.f;
            }
#pragma unroll
            for (int j = 0; j < EPT; j++)
                if (ok[j]) red_add_u64(&g_accum[d[j]], pack_msg(m[j]));
        } else {
            int cnt = (int)(E - base);
            for (int j = 0; j < cnt; j++) {
                int sj = __ldcs(p + base + j);
                int dj = __ldcs(p + E + base + j);
                if ((unsigned)sj < (unsigned)n && (unsigned)dj < (unsigned)n)
                    red_add_u64(&g_accum[dj], pack_msg(g_projl[sj]));
            }
        }
    } else {
        // ---- int64 path ----
        const long long* p = (const long long*)ei_raw;
        long long s[EPT], d[EPT];
        int cnt = (int)((base + EPT <= E) ? EPT : (E - base));
        if (cnt == EPT) {
#pragma unroll
            for (int j = 0; j < EPT; j += 2) {
                longlong2 sv = __ldcs((const longlong2*)(p + base + j));
                s[j] = sv.x; s[j + 1] = sv.y;
            }
#pragma unroll
            for (int j = 0; j < EPT; j += 2) {
                longlong2 dv = __ldcs((const longlong2*)(p + E + base + j));
                d[j] = dv.x; d[j + 1] = dv.y;
            }
        } else {
            for (int j = 0; j < cnt; j++) {
                s[j] = __ldcs(p + base + j);
                d[j] = __ldcs(p + E + base + j);
            }
        }
        float m[EPT];
        bool ok[EPT];
#pragma unroll
        for (int j = 0; j < EPT; j++) {
            ok[j] = (j < cnt) &&
                    (unsigned long long)s[j] < (unsigned long long)n &&
                    (unsigned long long)d[j] < (unsigned long long)n;
            m[j] = ok[j] ? g_projl[s[j]] : 0.f;
        }
#pragma unroll
        for (int j = 0; j < EPT; j++)
            if (ok[j]) red_add_u64(&g_accum[d[j]], pack_msg(m[j]));
    }
}

// ---------------------------------------------------------------------------
// Kernel 3: finalize, 2 nodes/thread with vector loads.
// unpack -> mean -> lin_l + lin_r -> elu -> out linear.
// ---------------------------------------------------------------------------
__global__ void k_final(float* __restrict__ out,
                        const float* __restrict__ bl,
                        const float* __restrict__ wo,
                        const float* __restrict__ bo,
                        int n) {
    int i0 = 2 * (blockIdx.x * blockDim.x + threadIdx.x);
    if (i0 >= n) return;
    float BL = __ldg(&bl[0]), WO = __ldg(&wo[0]), BO = __ldg(&bo[0]);

    if (i0 + 1 < n) {
        ulonglong2 ac = *(const ulonglong2*)&g_accum[i0];
        float2 pr = *(const float2*)&g_projr[i0];
        float r[2];
        unsigned long long a[2] = {ac.x, ac.y};
        float prv[2] = {pr.x, pr.y};
#pragma unroll
        for (int j = 0; j < 2; j++) {
            long long c = (long long)((a[j] + (1ULL << (CNT_SHIFT - 1))) >> CNT_SHIFT);
            long long sumfix = (long long)a[j] - (c << CNT_SHIFT);
            float mean = ((float)sumfix * FIX_INV) / fmaxf((float)c, 1.0f);
            float h = mean + BL + prv[j];
            h = (h > 0.f) ? h : expm1f(h);
            r[j] = fmaf(h, WO, BO);
        }
        *(float2*)&out[i0] = make_float2(r[0], r[1]);
    } else {
        unsigned long long acc = g_accum[i0];
        long long c = (long long)((acc + (1ULL << (CNT_SHIFT - 1))) >> CNT_SHIFT);
        long long sumfix = (long long)acc - (c << CNT_SHIFT);
        float mean = ((float)sumfix * FIX_INV) / fmaxf((float)c, 1.0f);
        float h = mean + BL + g_projr[i0];
        h = (h > 0.f) ? h : expm1f(h);
        out[i0] = fmaf(h, WO, BO);
    }
}

// ---------------------------------------------------------------------------
// Inputs (metadata order): x[N*17] f32, edge_index[2*E] int (width probed),
// edge_weight[E] f32 (UNUSED, faithful to PyG SAGEConv), w_l[17], b_l[1],
// w_r[17], w_o[1], b_o[1]. Output: [N] f32.
// ---------------------------------------------------------------------------
extern "C" void kernel_launch(void* const* d_in, const int* in_sizes, int n_in,
                              void* d_out, int out_size) {
    const float* x  = (const float*)d_in[0];
    const void*  ei = d_in[1];
    const float* wl = (const float*)d_in[3];
    const float* bl = (const float*)d_in[4];
    const float* wr = (const float*)d_in[5];
    const float* wo = (const float*)d_in[6];
    const float* bo = (const float*)d_in[7];
    float* out = (float*)d_out;

    int       n = in_sizes[0] / IN_DIM;
    long long E = (long long)in_sizes[1] / 2;   // element count is dtype-invariant
    long long totalF4 = (long long)in_sizes[0] / 4;

    int pblocks = (n + PROJ_TPB - 1) / PROJ_TPB;
    k_proj<<<pblocks, PROJ_TPB>>>((const float4*)x, totalF4, wl, wr,
                                  (const long long*)ei, n);

    const int TPB = 256;
    long long groups = (E + EPT - 1) / EPT;
    int eblocks = (int)((groups + TPB - 1) / TPB);
    k_edge<<<eblocks, TPB>>>(ei, E, n);

    int fblocks = (n / 2 + TPB - 1) / TPB;
    k_final<<<fblocks, TPB>>>(out, bl, wo, bo, n);
}

// round 13
// speedup vs baseline: 1.7535x; 1.7535x over previous
#include <cuda_runtime.h>
#include <cuda_bf16.h>
#include <math.h>

// Problem constants (from reference): N=500000, E=16000000, IN_DIM=17
#define NMAX 500000
#define IN_DIM 17

// Fixed-point packing: per-edge encoded value = round(msg * 2^24) + 2^40.
// Accumulator = cnt*2^40 + sum_fixed, |sum_fixed| < 2^39 always.
#define FIX_SCALE 16777216.0f           // 2^24
#define FIX_INV   (1.0f / 16777216.0f)
#define CNT_SHIFT 40

// Scratch (allocation-free rule: __device__ globals)
__device__ __align__(16) unsigned long long g_accum[NMAX];  // {count, fixed sum}
__device__ __align__(16) float g_projl[NMAX];               // x @ w_l^T
__device__ __align__(16) float g_projr[NMAX];               // x @ w_r^T
__device__ int g_use64;                                     // edge_index is int64?

// ---------------------------------------------------------------------------
// Kernel 1: projections + accumulator zero + (block 0) dtype probe.
// 4 consecutive nodes per thread = 68 floats = 17 ALIGNED float4 loads,
// all front-batched (MLP~17/thread). This exact form measured 13.0us in the
// 133.9us run; all k_proj variants sit at 12-13us (short-kernel DRAM
// ceiling), so no further redesign.
// ---------------------------------------------------------------------------
#define PROJ_TPB 128

__global__ void k_proj(const float4* __restrict__ x4,
                       const float* __restrict__ wl,
                       const float* __restrict__ wr,
                       const long long* __restrict__ ei,
                       int n) {
    if (blockIdx.x == 0 && threadIdx.x < 32) {
        // JAX without x64 silently downgrades the requested int64 edge_index
        // to int32; random int32 pairs read as int64 exceed [0,N) w.p. ~1.
        int bad = 0;
        for (int i = threadIdx.x; i < 2048; i += 32) {
            long long v = ei[i];
            if (v < 0 || v >= (long long)n) bad = 1;
        }
        bad = __any_sync(0xFFFFFFFFu, bad);
        if (threadIdx.x == 0) g_use64 = bad ? 0 : 1;
    }

    int t = blockIdx.x * PROJ_TPB + threadIdx.x;
    int i0 = t * 4;                       // first of 4 nodes
    if (i0 >= n) return;

    float wlv[IN_DIM], wrv[IN_DIM];
#pragma unroll
    for (int k = 0; k < IN_DIM; k++) { wlv[k] = __ldg(&wl[k]); wrv[k] = __ldg(&wr[k]); }

    if (i0 + 4 <= n) {
        // 17 aligned float4 loads cover exactly 4 rows (4*17 = 68 floats)
        float f[68];
        const float4* p = x4 + (long long)t * 17;
#pragma unroll
        for (int j = 0; j < 17; j++) {
            float4 v = p[j];
            f[4 * j]     = v.x; f[4 * j + 1] = v.y;
            f[4 * j + 2] = v.z; f[4 * j + 3] = v.w;
        }
        float pl4[4], pr4[4];
#pragma unroll
        for (int r = 0; r < 4; r++) {
            float pl = 0.f, pr = 0.f;
#pragma unroll
            for (int k = 0; k < IN_DIM; k++) {
                float v = f[17 * r + k];
                pl = fmaf(v, wlv[k], pl);
                pr = fmaf(v, wrv[k], pr);
            }
            pl4[r] = pl; pr4[r] = pr;
        }
        *(float4*)&g_projl[i0] = make_float4(pl4[0], pl4[1], pl4[2], pl4[3]);
        *(float4*)&g_projr[i0] = make_float4(pr4[0], pr4[1], pr4[2], pr4[3]);
        ulonglong2 z = make_ulonglong2(0ULL, 0ULL);
        *(ulonglong2*)&g_accum[i0]     = z;
        *(ulonglong2*)&g_accum[i0 + 2] = z;
    } else {
        const float* xf = (const float*)x4;
        for (int i = i0; i < n; i++) {
            float pl = 0.f, pr = 0.f;
            for (int k = 0; k < IN_DIM; k++) {
                float v = xf[(long long)i * IN_DIM + k];
                pl = fmaf(v, wlv[k], pl);
                pr = fmaf(v, wrv[k], pr);
            }
            g_projl[i] = pl; g_projr[i] = pr; g_accum[i] = 0ULL;
        }
    }
}

// ---------------------------------------------------------------------------
// Kernel 2: edge scatter. 8 edges/thread (EPT=16 regressed; 8 is the sweet
// spot). Phase order maximizes MLP: vector-load all indices, issue ALL 8
// gathers of proj_l, then fire 8 fire-and-forget u64 REDs (packed fixed-
// point sum + count). Bound: LTS sector throughput — gather 16M + RED 16M
// 32B sectors ~= 1 GB of L2 traffic, ~90% of the chip LTS cap. FROZEN.
// ---------------------------------------------------------------------------
#define EPT 8

__device__ __forceinline__ void red_add_u64(unsigned long long* addr,
                                            unsigned long long v) {
    asm volatile("red.global.add.u64 [%0], %1;" :: "l"(addr), "l"(v) : "memory");
}

__device__ __forceinline__ unsigned long long pack_msg(float msg) {
    return (unsigned long long)(llrintf(msg * FIX_SCALE) + (1LL << CNT_SHIFT));
}

__global__ void k_edge(const void* __restrict__ ei_raw, long long E, int n) {
    long long base = (long long)EPT * ((long long)blockIdx.x * blockDim.x + threadIdx.x);
    if (base >= E) return;

    if (!g_use64) {
        // ---- int32 fast path (expected) ----
        const int* p = (const int*)ei_raw;
        if (base + EPT <= E) {
            int s[EPT], d[EPT];
#pragma unroll
            for (int j = 0; j < EPT; j += 4) {
                int4 sv = __ldcs((const int4*)(p + base + j));
                s[j] = sv.x; s[j + 1] = sv.y; s[j + 2] = sv.z; s[j + 3] = sv.w;
            }
#pragma unroll
            for (int j = 0; j < EPT; j += 4) {
                int4 dv = __ldcs((const int4*)(p + E + base + j));
                d[j] = dv.x; d[j + 1] = dv.y; d[j + 2] = dv.z; d[j + 3] = dv.w;
            }
            float m[EPT];
            bool ok[EPT];
#pragma unroll
            for (int j = 0; j < EPT; j++) {
                ok[j] = (unsigned)s[j] < (unsigned)n && (unsigned)d[j] < (unsigned)n;
                m[j] = ok[j] ? g_projl[s[j]] : 0.f;
            }
#pragma unroll
            for (int j = 0; j < EPT; j++)
                if (ok[j]) red_add_u64(&g_accum[d[j]], pack_msg(m[j]));
        } else {
            int cnt = (int)(E - base);
            for (int j = 0; j < cnt; j++) {
                int sj = __ldcs(p + base + j);
                int dj = __ldcs(p + E + base + j);
                if ((unsigned)sj < (unsigned)n && (unsigned)dj < (unsigned)n)
                    red_add_u64(&g_accum[dj], pack_msg(g_projl[sj]));
            }
        }
    } else {
        // ---- int64 path ----
        const long long* p = (const long long*)ei_raw;
        long long s[EPT], d[EPT];
        int cnt = (int)((base + EPT <= E) ? EPT : (E - base));
        if (cnt == EPT) {
#pragma unroll
            for (int j = 0; j < EPT; j += 2) {
                longlong2 sv = __ldcs((const longlong2*)(p + base + j));
                s[j] = sv.x; s[j + 1] = sv.y;
            }
#pragma unroll
            for (int j = 0; j < EPT; j += 2) {
                longlong2 dv = __ldcs((const longlong2*)(p + E + base + j));
                d[j] = dv.x; d[j + 1] = dv.y;
            }
        } else {
            for (int j = 0; j < cnt; j++) {
                s[j] = __ldcs(p + base + j);
                d[j] = __ldcs(p + E + base + j);
            }
        }
        float m[EPT];
        bool ok[EPT];
#pragma unroll
        for (int j = 0; j < EPT; j++) {
            ok[j] = (j < cnt) &&
                    (unsigned long long)s[j] < (unsigned long long)n &&
                    (unsigned long long)d[j] < (unsigned long long)n;
            m[j] = ok[j] ? g_projl[s[j]] : 0.f;
        }
#pragma unroll
        for (int j = 0; j < EPT; j++)
            if (ok[j]) red_add_u64(&g_accum[d[j]], pack_msg(m[j]));
    }
}

// ---------------------------------------------------------------------------
// Kernel 3: finalize, 2 nodes/thread with vector loads.
// unpack -> mean -> lin_l + lin_r -> elu -> out linear.
// ---------------------------------------------------------------------------
__global__ void k_final(float* __restrict__ out,
                        const float* __restrict__ bl,
                        const float* __restrict__ wo,
                        const float* __restrict__ bo,
                        int n) {
    int i0 = 2 * (blockIdx.x * blockDim.x + threadIdx.x);
    if (i0 >= n) return;
    float BL = __ldg(&bl[0]), WO = __ldg(&wo[0]), BO = __ldg(&bo[0]);

    if (i0 + 1 < n) {
        ulonglong2 ac = *(const ulonglong2*)&g_accum[i0];
        float2 pr = *(const float2*)&g_projr[i0];
        float r[2];
        unsigned long long a[2] = {ac.x, ac.y};
        float prv[2] = {pr.x, pr.y};
#pragma unroll
        for (int j = 0; j < 2; j++) {
            long long c = (long long)((a[j] + (1ULL << (CNT_SHIFT - 1))) >> CNT_SHIFT);
            long long sumfix = (long long)a[j] - (c << CNT_SHIFT);
            float mean = ((float)sumfix * FIX_INV) / fmaxf((float)c, 1.0f);
            float h = mean + BL + prv[j];
            h = (h > 0.f) ? h : expm1f(h);
            r[j] = fmaf(h, WO, BO);
        }
        *(float2*)&out[i0] = make_float2(r[0], r[1]);
    } else {
        unsigned long long acc = g_accum[i0];
        long long c = (long long)((acc + (1ULL << (CNT_SHIFT - 1))) >> CNT_SHIFT);
        long long sumfix = (long long)acc - (c << CNT_SHIFT);
        float mean = ((float)sumfix * FIX_INV) / fmaxf((float)c, 1.0f);
        float h = mean + BL + g_projr[i0];
        h = (h > 0.f) ? h : expm1f(h);
        out[i0] = fmaf(h, WO, BO);
    }
}

// ---------------------------------------------------------------------------
// Inputs (metadata order): x[N*17] f32, edge_index[2*E] int (width probed),
// edge_weight[E] f32 (UNUSED, faithful to PyG SAGEConv), w_l[17], b_l[1],
// w_r[17], w_o[1], b_o[1]. Output: [N] f32.
// ---------------------------------------------------------------------------
extern "C" void kernel_launch(void* const* d_in, const int* in_sizes, int n_in,
                              void* d_out, int out_size) {
    const float* x  = (const float*)d_in[0];
    const void*  ei = d_in[1];
    const float* wl = (const float*)d_in[3];
    const float* bl = (const float*)d_in[4];
    const float* wr = (const float*)d_in[5];
    const float* wo = (const float*)d_in[6];
    const float* bo = (const float*)d_in[7];
    float* out = (float*)d_out;

    int       n = in_sizes[0] / IN_DIM;
    long long E = (long long)in_sizes[1] / 2;   // element count is dtype-invariant

    int nquads = (n + 3) / 4;
    int pblocks = (nquads + PROJ_TPB - 1) / PROJ_TPB;
    k_proj<<<pblocks, PROJ_TPB>>>((const float4*)x, wl, wr,
                                  (const long long*)ei, n);

    const int TPB = 256;
    long long groups = (E + EPT - 1) / EPT;
    int eblocks = (int)((groups + TPB - 1) / TPB);
    k_edge<<<eblocks, TPB>>>(ei, E, n);

    int fblocks = (n / 2 + TPB - 1) / TPB;
    k_final<<<fblocks, TPB>>>(out, bl, wo, bo, n);
}